// round 16
// baseline (speedup 1.0000x reference)
#include <cuda_runtime.h>
#include <cstdint>

// Fixed shapes for TopKGOATLayer_74156905333517
#define T_TOK   8192
#define DMODEL  4096
#define N_EXP   8
#define RANK    64
#define ER      512
#define KSPLIT  8
#define KCH_G   (DMODEL / KSPLIT)   // 512, gate k-chunk
#define NPAIR   64                  // ordered expert pairs e1*8+e2
#define CAP     1024                // tokens per pair-list (expected ~146)
#define MAXTIL  8                   // CAP/128 tiles per pair-list
#define KS1     4                   // K-split factor for gemm1
#define KCHUNK  (DMODEL / KS1)
#define HROW    128                 // H row length (2 slots x RANK)
#define HP_STRIDE ((size_t)NPAIR * CAP * HROW)

// Scratch (__device__ globals)
__device__ __align__(16) float g_Ar[ER * DMODEL];             // tf32 lora_A
__device__ __align__(16) float g_Br[N_EXP * DMODEL * RANK];   // tf32 lora_B
__device__ __align__(16) float g_Hp[KS1 * NPAIR * CAP * HROW];// gemm1 partials
__device__ __align__(16) float g_H[NPAIR * CAP * HROW];       // weighted H
__device__ float g_lp[KSPLIT * T_TOK * N_EXP];
__device__ int   g_cnt[NPAIR];
__device__ int   g_list[NPAIR * CAP];
__device__ float g_w1[NPAIR * CAP];

// ---------------------------------------------------------------------------
// helpers
// ---------------------------------------------------------------------------
__device__ __forceinline__ unsigned f2tf(float f) {
    unsigned r;
    asm("cvt.rna.tf32.f32 %0, %1;" : "=r"(r) : "f"(f));
    return r;
}

__device__ __forceinline__ void mma_tf32(float c[4], const unsigned a[4], const unsigned b[2]) {
    asm volatile(
        "mma.sync.aligned.m16n8k8.row.col.f32.tf32.tf32.f32 "
        "{%0,%1,%2,%3}, {%4,%5,%6,%7}, {%8,%9}, {%0,%1,%2,%3};\n"
        : "+f"(c[0]), "+f"(c[1]), "+f"(c[2]), "+f"(c[3])
        : "r"(a[0]), "r"(a[1]), "r"(a[2]), "r"(a[3]), "r"(b[0]), "r"(b[1]));
}

__device__ __forceinline__ void cp_async16(uint32_t saddr, const void* gaddr) {
    asm volatile("cp.async.cg.shared.global [%0], [%1], 16;\n" :: "r"(saddr), "l"(gaddr));
}
__device__ __forceinline__ void cp_commit() { asm volatile("cp.async.commit_group;\n"); }
template <int N> __device__ __forceinline__ void cp_wait() {
    asm volatile("cp.async.wait_group %0;\n" :: "n"(N));
}

// ---------------------------------------------------------------------------
// tf32 pre-rounding of LoRA weights + pair-counter reset
// ---------------------------------------------------------------------------
__global__ __launch_bounds__(256) void round_weights(const float4* __restrict__ lA,
                                                     const float4* __restrict__ lB,
                                                     float4* __restrict__ Ar,
                                                     float4* __restrict__ Br,
                                                     int* __restrict__ cnt)
{
    const int n4 = ER * DMODEL / 4;
    int i = blockIdx.x * 256 + threadIdx.x;
    if (i < n4) {
        float4 v = lA[i];
        v.x = __uint_as_float(f2tf(v.x));
        v.y = __uint_as_float(f2tf(v.y));
        v.z = __uint_as_float(f2tf(v.z));
        v.w = __uint_as_float(f2tf(v.w));
        Ar[i] = v;
        float4 u = lB[i];
        u.x = __uint_as_float(f2tf(u.x));
        u.y = __uint_as_float(f2tf(u.y));
        u.z = __uint_as_float(f2tf(u.z));
        u.w = __uint_as_float(f2tf(u.w));
        Br[i] = u;
    }
    if (blockIdx.x == 0 && threadIdx.x < NPAIR) cnt[threadIdx.x] = 0;
}

// ---------------------------------------------------------------------------
// Gate partials — streaming. grid = (T/64, KSPLIT=8), 256 thr.
// ---------------------------------------------------------------------------
__global__ __launch_bounds__(256) void gate_part(const float* __restrict__ x,
                                                 const float* __restrict__ gw,
                                                 float* __restrict__ lp)
{
    __shared__ float gs[N_EXP][KCH_G];   // 16 KB

    const int tid  = threadIdx.x;
    const int lane = tid & 31;
    const int warp = tid >> 5;
    const int tok0 = blockIdx.x * 64 + warp * 8;
    const int kc0  = blockIdx.y * KCH_G;

#pragma unroll
    for (int j = 0; j < 4; j++) {
        int li  = tid + j * 256;
        int row = li >> 7;
        int col = (li & 127) * 4;
        *(float4*)&gs[row][col] = *(const float4*)&gw[(size_t)row * DMODEL + kc0 + col];
    }
    __syncthreads();

    float acc[8][8];
#pragma unroll
    for (int i = 0; i < 8; i++)
#pragma unroll
        for (int e = 0; e < 8; e++) acc[i][e] = 0.f;

    const float* xp[8];
#pragma unroll
    for (int i = 0; i < 8; i++)
        xp[i] = &x[(size_t)(tok0 + i) * DMODEL + kc0 + lane];

#pragma unroll 4
    for (int h = 0; h < KCH_G / 32; h++) {
        float xv[8];
#pragma unroll
        for (int i = 0; i < 8; i++) xv[i] = xp[i][h * 32];
        float gv[8];
#pragma unroll
        for (int e = 0; e < 8; e++) gv[e] = gs[e][h * 32 + lane];
#pragma unroll
        for (int i = 0; i < 8; i++)
#pragma unroll
            for (int e = 0; e < 8; e++) acc[i][e] += xv[i] * gv[e];
    }

#pragma unroll
    for (int off = 16; off > 0; off >>= 1)
#pragma unroll
        for (int i = 0; i < 8; i++)
#pragma unroll
            for (int e = 0; e < 8; e++)
                acc[i][e] += __shfl_xor_sync(0xffffffffu, acc[i][e], off);

#pragma unroll
    for (int i = 0; i < 8; i++) {
        if (lane == i) {
            int tok = tok0 + i;
            size_t base = ((size_t)blockIdx.y * T_TOK + tok) * N_EXP;
#pragma unroll
            for (int e = 0; e < 8; e++) lp[base + e] = acc[i][e];
        }
    }
}

// ---------------------------------------------------------------------------
// Gate finalize + scatter into PAIR lists (one atomic per token).
// p = e1*8 + e2 (e1 = top-1, e2 = top-2). w1 stored; w2 = 1 - w1.
// ---------------------------------------------------------------------------
__global__ __launch_bounds__(256) void gate_fin(const float* __restrict__ lp,
                                                int* __restrict__ cnt,
                                                int* __restrict__ list,
                                                float* __restrict__ w1l)
{
    const int tok = blockIdx.x * 256 + threadIdx.x;
    float l[8];
#pragma unroll
    for (int e = 0; e < 8; e++) l[e] = 0.f;
#pragma unroll
    for (int s = 0; s < KSPLIT; s++) {
        size_t base = ((size_t)s * T_TOK + tok) * N_EXP;
#pragma unroll
        for (int e = 0; e < 8; e++) l[e] += lp[base + e];
    }
    float m1 = -1e30f; int e1 = 0;
#pragma unroll
    for (int e = 0; e < 8; e++)
        if (l[e] > m1) { m1 = l[e]; e1 = e; }
    float m2 = -1e30f; int e2 = 0;
#pragma unroll
    for (int e = 0; e < 8; e++)
        if (e != e1 && l[e] > m2) { m2 = l[e]; e2 = e; }
    float w1 = 1.0f / (1.0f + __expf(m2 - m1));

    int p = e1 * N_EXP + e2;
    int pos = atomicAdd(&cnt[p], 1);
    if (pos < CAP) {
        list[p * CAP + pos] = tok;
        w1l[p * CAP + pos] = w1;
    }
}

// ---------------------------------------------------------------------------
// GEMM1 sparse — same mainloop as the 74.5us config; pair-list indexing.
// grid.x = KS1(4) x SLOT(2) x NPAIR(64) x MAXTIL(8) = 4096.
// Writes Hp rows of stride 128, cols [slot*64, slot*64+64).
// ---------------------------------------------------------------------------
#define G1_AT (128 * 36)
#define G1_BT (64 * 36)
#define G1_ST (G1_AT + G1_BT)
#define G1_DYN (2 * G1_ST * 4)

__global__ __launch_bounds__(128, 4) void gemm1_sparse(const float* __restrict__ x,
                                                       const float* __restrict__ Ar,
                                                       const int* __restrict__ cnt,
                                                       const int* __restrict__ list,
                                                       float* __restrict__ Hp)
{
    const int bx   = blockIdx.x;
    const int ks   = bx >> 10;
    const int rem  = bx & 1023;
    const int slot = rem >> 9;
    const int rem2 = rem & 511;
    const int p    = rem2 >> 3;
    const int mt   = rem2 & (MAXTIL - 1);
    const int n    = min(cnt[p], CAP);
    if (mt * 128 >= n) return;
    const int e = slot ? (p & 7) : (p >> 3);

    __shared__ int toks[128];
    extern __shared__ float sm[];

    const int tid  = threadIdx.x;
    const int lane = tid & 31;
    const int warp = tid >> 5;
    const int wm   = warp >> 1;
    const int wn   = warp & 1;

    toks[tid] = list[p * CAP + mt * 128 + tid];
    __syncthreads();

    const uint32_t smbase = (uint32_t)__cvta_generic_to_shared(sm);
    const int lr4 = tid >> 3;
    const int lc4 = (tid & 7) * 4;
    const int kb  = ks * KCHUNK;

    const float* ap[8];
#pragma unroll
    for (int j = 0; j < 8; j++)
        ap[j] = &x[(size_t)toks[lr4 + j * 16] * DMODEL + kb + lc4];
    const float* bp[4];
#pragma unroll
    for (int j = 0; j < 4; j++)
        bp[j] = &Ar[((size_t)e * 64 + lr4 + j * 16) * DMODEL + kb + lc4];

    auto issue = [&](int kt) {
        const int s = kt & 1;
        const int k0 = kt * 32;
        const uint32_t sa = smbase + (uint32_t)(s * G1_ST) * 4u;
        const uint32_t sb = sa + G1_AT * 4u;
#pragma unroll
        for (int j = 0; j < 8; j++)
            cp_async16(sa + ((lr4 + j * 16) * 36 + lc4) * 4u, ap[j] + k0);
#pragma unroll
        for (int j = 0; j < 4; j++)
            cp_async16(sb + ((lr4 + j * 16) * 36 + lc4) * 4u, bp[j] + k0);
    };

    float c[4][4][4] = {};
    issue(0); cp_commit();

    const int r0 = lane >> 2;
    const int cq = lane & 3;
    constexpr int KT = KCHUNK / 32;

    for (int kt = 0; kt < KT; kt++) {
        if (kt + 1 < KT) { issue(kt + 1); cp_commit(); cp_wait<1>(); }
        else             { cp_wait<0>(); }
        __syncthreads();

        const float* As = sm + (kt & 1) * G1_ST;
        const float* Bs = As + G1_AT;

#pragma unroll
        for (int kk = 0; kk < 4; kk++) {
            const int k8 = kk * 8;
            unsigned a[4][4], b[4][2];
#pragma unroll
            for (int mi = 0; mi < 4; mi++) {
                int rb = wm * 64 + mi * 16 + r0;
                a[mi][0] = __float_as_uint(As[rb * 36 + k8 + cq]);
                a[mi][1] = __float_as_uint(As[(rb + 8) * 36 + k8 + cq]);
                a[mi][2] = __float_as_uint(As[rb * 36 + k8 + cq + 4]);
                a[mi][3] = __float_as_uint(As[(rb + 8) * 36 + k8 + cq + 4]);
            }
#pragma unroll
            for (int ni = 0; ni < 4; ni++) {
                int nb = wn * 32 + ni * 8 + r0;
                b[ni][0] = __float_as_uint(Bs[nb * 36 + k8 + cq]);
                b[ni][1] = __float_as_uint(Bs[nb * 36 + k8 + cq + 4]);
            }
#pragma unroll
            for (int mi = 0; mi < 4; mi++)
#pragma unroll
                for (int ni = 0; ni < 4; ni++)
                    mma_tf32(c[mi][ni], a[mi], b[ni]);
        }
        __syncthreads();
    }

    const size_t base = (size_t)ks * HP_STRIDE
                      + ((size_t)p * CAP + mt * 128) * HROW + slot * 64;
#pragma unroll
    for (int mi = 0; mi < 4; mi++) {
#pragma unroll
        for (int ni = 0; ni < 4; ni++) {
            int row = wm * 64 + mi * 16 + r0;
            int col = wn * 32 + ni * 8 + cq * 2;
            *(float2*)&Hp[base + (size_t)row * HROW + col] =
                make_float2(c[mi][ni][0], c[mi][ni][1]);
            *(float2*)&Hp[base + (size_t)(row + 8) * HROW + col] =
                make_float2(c[mi][ni][2], c[mi][ni][3]);
        }
    }
}

// ---------------------------------------------------------------------------
// reduce_H: H[p][i][k] = round( w * sum_ks Hp[ks][p][i][k] ),
// w = w1 for k<64, w = (1-w1) for k>=64.  grid = NPAIR*MAXTIL, 256 thr.
// ---------------------------------------------------------------------------
__global__ __launch_bounds__(256) void reduce_H(const float* __restrict__ Hp,
                                                const int* __restrict__ cnt,
                                                const float* __restrict__ w1l,
                                                float* __restrict__ H)
{
    const int p  = blockIdx.x >> 3;
    const int mt = blockIdx.x & (MAXTIL - 1);
    const int n  = min(cnt[p], CAP);
    if (mt * 128 >= n) return;

    const int tid  = threadIdx.x;
    const int row  = tid >> 1;
    const int half = (tid & 1) * 64;
    const int i    = mt * 128 + row;
    if (i >= n) return;

    const float w1 = w1l[p * CAP + i];
    const float w  = (tid & 1) ? (1.0f - w1) : w1;
    const size_t rb = ((size_t)p * CAP + i) * HROW + half;

#pragma unroll
    for (int q = 0; q < 16; q++) {
        float4 s = *(const float4*)&Hp[rb + q * 4];
#pragma unroll
        for (int ks = 1; ks < KS1; ks++) {
            float4 pp = *(const float4*)&Hp[(size_t)ks * HP_STRIDE + rb + q * 4];
            s.x += pp.x; s.y += pp.y; s.z += pp.z; s.w += pp.w;
        }
        s.x = __uint_as_float(f2tf(s.x * w));
        s.y = __uint_as_float(f2tf(s.y * w));
        s.z = __uint_as_float(f2tf(s.z * w));
        s.w = __uint_as_float(f2tf(s.w * w));
        *(float4*)&H[rb + q * 4] = s;
    }
}

// ---------------------------------------------------------------------------
// GEMM2 single-pass: out[tok] = H[p][i][0:128] @ concat(B_e1, B_e2)^T tile.
// M=128 tokens, N=128 cols, K=128 one-shot. 4 N-tiles/CTA, B double-buffered.
// H tile loaded once. Single writer per out element -> no second pass.
// 256 thr (8 warps 2x4), 1 CTA/SM (203 KB smem).
// ---------------------------------------------------------------------------
#define NT2   4
#define G2_T  (128 * 132)                // floats per (H or B) tile buffer
#define G2_DYN (3 * G2_T * 4)            // H + Bb0 + Bb1 = 202752 B
#define SO_S  132

__global__ __launch_bounds__(256, 1) void gemm2_single(const float* __restrict__ H,
                                                       const float* __restrict__ Br,
                                                       const int* __restrict__ cnt,
                                                       const int* __restrict__ list,
                                                       float* __restrict__ out)
{
    const int p  = blockIdx.y >> 3;
    const int mt = blockIdx.y & (MAXTIL - 1);
    const int n  = min(cnt[p], CAP);
    if (mt * 128 >= n) return;
    const int e1 = p >> 3;
    const int e2 = p & 7;
    const int bn0 = blockIdx.x * (NT2 * 128);

    __shared__ int toks[128];
    extern __shared__ float sm[];
    float* Hs = sm;                       // H tile (persistent)

    const int tid  = threadIdx.x;
    const int lane = tid & 31;
    const int warp = tid >> 5;
    const int wm   = warp >> 2;
    const int wn   = warp & 3;

    if (tid < 128) toks[tid] = list[p * CAP + mt * 128 + tid];

    const uint32_t smbase = (uint32_t)__cvta_generic_to_shared(sm);
    const int hr = tid >> 1;           // 0..127
    const int hc = (tid & 1) * 64;     // 0 or 64

    auto issueB = [&](int t) {
        const uint32_t boff = (uint32_t)((1 + (t & 1)) * G2_T) * 4u;
        const float* bsrc = (tid & 1)
            ? &Br[((size_t)e2 * DMODEL + bn0 + t * 128 + hr) * RANK]
            : &Br[((size_t)e1 * DMODEL + bn0 + t * 128 + hr) * RANK];
#pragma unroll
        for (int j = 0; j < 16; j++)
            cp_async16(smbase + boff + (uint32_t)(hr * 132 + hc + j * 4) * 4u,
                       bsrc + j * 4);
    };

    // G0 = {H, B0}
    {
        const float* hsrc = &H[((size_t)p * CAP + mt * 128 + hr) * HROW + hc];
#pragma unroll
        for (int j = 0; j < 16; j++)
            cp_async16(smbase + (uint32_t)(hr * 132 + hc + j * 4) * 4u, hsrc + j * 4);
    }
    issueB(0);
    cp_commit();
    issueB(1);
    cp_commit();

    const int r0 = lane >> 2;
    const int cq = lane & 3;
    const int rr = tid >> 3;            // 0..31 (epilogue row)
    const int kk8 = (tid & 7) * 4;      // 0..28

#pragma unroll 1
    for (int t = 0; t < NT2; t++) {
        if (t < NT2 - 1) cp_wait<1>();
        else             cp_wait<0>();
        __syncthreads();

        const float* Bs = sm + (1 + (t & 1)) * G2_T;
        float* so = sm + (1 + (t & 1)) * G2_T;   // staging = this tile's B buf
        const int bn = bn0 + t * 128;

        float c[4][4][4] = {};
#pragma unroll
        for (int kk = 0; kk < 16; kk++) {
            const int k8 = kk * 8;
            unsigned a[4][4], b[4][2];
#pragma unroll
            for (int mi = 0; mi < 4; mi++) {
                int rb = wm * 64 + mi * 16 + r0;
                a[mi][0] = __float_as_uint(Hs[rb * 132 + k8 + cq]);
                a[mi][1] = __float_as_uint(Hs[(rb + 8) * 132 + k8 + cq]);
                a[mi][2] = __float_as_uint(Hs[rb * 132 + k8 + cq + 4]);
                a[mi][3] = __float_as_uint(Hs[(rb + 8) * 132 + k8 + cq + 4]);
            }
#pragma unroll
            for (int ni = 0; ni < 4; ni++) {
                int nb = wn * 32 + ni * 8 + r0;
                b[ni][0] = __float_as_uint(Bs[nb * 132 + k8 + cq]);
                b[ni][1] = __float_as_uint(Bs[nb * 132 + k8 + cq + 4]);
            }
#pragma unroll
            for (int mi = 0; mi < 4; mi++)
#pragma unroll
                for (int ni = 0; ni < 4; ni++)
                    mma_tf32(c[mi][ni], a[mi], b[ni]);
        }

        // ---- staged coalesced epilogue: 4 groups of 32 rows ----
#pragma unroll
        for (int g = 0; g < 4; g++) {
            __syncthreads();
            if (wm == (g >> 1)) {
                const int m0 = (g & 1) * 2;
#pragma unroll
                for (int mh = 0; mh < 2; mh++) {
                    const int mi = m0 + mh;
                    const int rl = mh * 16 + r0;
#pragma unroll
                    for (int ni = 0; ni < 4; ni++) {
                        const int col = wn * 32 + ni * 8 + cq * 2;
                        *(float2*)&so[rl * SO_S + col] =
                            make_float2(c[mi][ni][0], c[mi][ni][1]);
                        *(float2*)&so[(rl + 8) * SO_S + col] =
                            make_float2(c[mi][ni][2], c[mi][ni][3]);
                    }
                }
            }
            __syncthreads();
            const int gi = mt * 128 + g * 32 + rr;
            if (gi < n) {
                const int tk = toks[g * 32 + rr];
                float* op = &out[(size_t)tk * DMODEL + bn + kk8];
#pragma unroll
                for (int q = 0; q < 4; q++) {
                    float4 v = *(float4*)&so[rr * SO_S + kk8 + q * 32];
                    *(float4*)&op[q * 32] = v;
                }
            }
        }
        __syncthreads();   // epilogue drained before buffer (t&1) is refilled

        if (t + 2 < NT2) { issueB(t + 2); cp_commit(); }
    }
}

// ---------------------------------------------------------------------------
// launch
// ---------------------------------------------------------------------------
extern "C" void kernel_launch(void* const* d_in, const int* in_sizes, int n_in,
                              void* d_out, int out_size)
{
    const float* x  = (const float*)d_in[0];   // [4,2048,4096]
    const float* gw = (const float*)d_in[1];   // [8,4096]
    const float* lA = (const float*)d_in[2];   // [8,64,4096]
    const float* lB = (const float*)d_in[3];   // [8,4096,64]
    float* out = (float*)d_out;

    float *Hp, *Hc, *lpp, *Ar, *Br, *w1p;
    int *cntp, *listp;
    cudaGetSymbolAddress((void**)&Hp,   g_Hp);
    cudaGetSymbolAddress((void**)&Hc,   g_H);
    cudaGetSymbolAddress((void**)&lpp,  g_lp);
    cudaGetSymbolAddress((void**)&Ar,   g_Ar);
    cudaGetSymbolAddress((void**)&Br,   g_Br);
    cudaGetSymbolAddress((void**)&cntp, g_cnt);
    cudaGetSymbolAddress((void**)&listp,g_list);
    cudaGetSymbolAddress((void**)&w1p,  g_w1);

    cudaFuncSetAttribute((const void*)gemm1_sparse,
                         cudaFuncAttributeMaxDynamicSharedMemorySize, G1_DYN);
    cudaFuncSetAttribute((const void*)gemm2_single,
                         cudaFuncAttributeMaxDynamicSharedMemorySize, G2_DYN);

    // 1) round LoRA weights to tf32 + reset pair counters
    round_weights<<<(ER * DMODEL / 4 + 255) / 256, 256>>>(
        (const float4*)lA, (const float4*)lB, (float4*)Ar, (float4*)Br, cntp);
    // 2) gate partials (streaming, K-split x8)
    gate_part<<<dim3(T_TOK / 64, KSPLIT), 256>>>(x, gw, lpp);
    // 3) finalize gate + scatter into pair lists (one atomic per token)
    gate_fin<<<T_TOK / 256, 256>>>(lpp, cntp, listp, w1p);
    // 4) sparse GEMM1: per (ks, slot, pair, mt)
    gemm1_sparse<<<KS1 * 2 * NPAIR * MAXTIL, 128, G1_DYN>>>(x, Ar, cntp, listp, Hp);
    // 5) reduce partials + per-slot routing weights + tf32-round
    reduce_H<<<NPAIR * MAXTIL, 256>>>(Hp, cntp, w1p, Hc);
    // 6) single-pass GEMM2 (K=128): out written exactly once
    gemm2_single<<<dim3(DMODEL / (NT2 * 128), NPAIR * MAXTIL), 256, G2_DYN>>>(
        Hc, Br, cntp, listp, out);
}

// round 17
// speedup vs baseline: 2.3555x; 2.3555x over previous
#include <cuda_runtime.h>
#include <cstdint>

// Fixed shapes for TopKGOATLayer_74156905333517
#define T_TOK   8192
#define DMODEL  4096
#define N_EXP   8
#define RANK    64
#define ER      512
#define KSPLIT  8
#define KCH_G   (DMODEL / KSPLIT)   // 512, gate k-chunk
#define MAXTIL  64          // worst-case M-tiles per list (8192/128)
#define NLIST   16          // (slot, expert)
#define KS1     4           // K-split factor for gemm1
#define KCHUNK  (DMODEL / KS1)
#define HP_STRIDE ((size_t)NLIST * T_TOK * RANK)

// Scratch (__device__ globals)
__device__ __align__(16) float g_Ar[ER * DMODEL];           // tf32-rounded lora_A
__device__ __align__(16) float g_Br[N_EXP * DMODEL * RANK]; // tf32-rounded lora_B
__device__ __align__(16) float g_Hp[KS1 * NLIST * T_TOK * RANK]; // gemm1 partials
__device__ __align__(16) float g_H[NLIST * T_TOK * RANK];   // compact Hw per (slot,e)
__device__ float g_lp[KSPLIT * T_TOK * N_EXP];
__device__ int   g_cnt[NLIST];
__device__ int   g_list[NLIST * T_TOK];
__device__ float g_wl[NLIST * T_TOK];

// ---------------------------------------------------------------------------
// helpers
// ---------------------------------------------------------------------------
__device__ __forceinline__ unsigned f2tf(float f) {
    unsigned r;
    asm("cvt.rna.tf32.f32 %0, %1;" : "=r"(r) : "f"(f));
    return r;
}

__device__ __forceinline__ void mma_tf32(float c[4], const unsigned a[4], const unsigned b[2]) {
    asm volatile(
        "mma.sync.aligned.m16n8k8.row.col.f32.tf32.tf32.f32 "
        "{%0,%1,%2,%3}, {%4,%5,%6,%7}, {%8,%9}, {%0,%1,%2,%3};\n"
        : "+f"(c[0]), "+f"(c[1]), "+f"(c[2]), "+f"(c[3])
        : "r"(a[0]), "r"(a[1]), "r"(a[2]), "r"(a[3]), "r"(b[0]), "r"(b[1]));
}

__device__ __forceinline__ void cp_async16(uint32_t saddr, const void* gaddr) {
    asm volatile("cp.async.cg.shared.global [%0], [%1], 16;\n" :: "r"(saddr), "l"(gaddr));
}
__device__ __forceinline__ void cp_commit() { asm volatile("cp.async.commit_group;\n"); }
template <int N> __device__ __forceinline__ void cp_wait() {
    asm volatile("cp.async.wait_group %0;\n" :: "n"(N));
}

// ---------------------------------------------------------------------------
// Gate partials (blockIdx.y < KSPLIT) + fused weight rounding row
// (blockIdx.y == KSPLIT; independent work overlapped with the gate).
// grid = (T/64 = 128, KSPLIT+1), 256 thr.
// ---------------------------------------------------------------------------
__global__ __launch_bounds__(256) void gate_part(const float* __restrict__ x,
                                                 const float* __restrict__ gw,
                                                 float* __restrict__ lp,
                                                 const float4* __restrict__ lA,
                                                 const float4* __restrict__ lB,
                                                 float4* __restrict__ Ar,
                                                 float4* __restrict__ Br,
                                                 int* __restrict__ cnt)
{
    __shared__ float gs[N_EXP][KCH_G];   // 16 KB

    const int tid  = threadIdx.x;

    if (blockIdx.y == KSPLIT) {
        // ---- weight rounding row: 128 blocks x 256 thr, 16 float4 each ----
        const int n4 = ER * DMODEL / 4;          // 524288
        int base = blockIdx.x * 256 + tid;       // 0..32767
#pragma unroll 4
        for (int i = base; i < n4; i += 128 * 256) {
            float4 v = lA[i];
            v.x = __uint_as_float(f2tf(v.x));
            v.y = __uint_as_float(f2tf(v.y));
            v.z = __uint_as_float(f2tf(v.z));
            v.w = __uint_as_float(f2tf(v.w));
            Ar[i] = v;
            float4 u = lB[i];
            u.x = __uint_as_float(f2tf(u.x));
            u.y = __uint_as_float(f2tf(u.y));
            u.z = __uint_as_float(f2tf(u.z));
            u.w = __uint_as_float(f2tf(u.w));
            Br[i] = u;
        }
        if (blockIdx.x == 0 && tid < NLIST) cnt[tid] = 0;
        return;
    }

    const int lane = tid & 31;
    const int warp = tid >> 5;
    const int tok0 = blockIdx.x * 64 + warp * 8;
    const int kc0  = blockIdx.y * KCH_G;

#pragma unroll
    for (int j = 0; j < 4; j++) {
        int li  = tid + j * 256;
        int row = li >> 7;
        int col = (li & 127) * 4;
        *(float4*)&gs[row][col] = *(const float4*)&gw[(size_t)row * DMODEL + kc0 + col];
    }
    __syncthreads();

    float acc[8][8];
#pragma unroll
    for (int i = 0; i < 8; i++)
#pragma unroll
        for (int e = 0; e < 8; e++) acc[i][e] = 0.f;

    const float* xp[8];
#pragma unroll
    for (int i = 0; i < 8; i++)
        xp[i] = &x[(size_t)(tok0 + i) * DMODEL + kc0 + lane];

#pragma unroll 4
    for (int h = 0; h < KCH_G / 32; h++) {
        float xv[8];
#pragma unroll
        for (int i = 0; i < 8; i++) xv[i] = xp[i][h * 32];
        float gv[8];
#pragma unroll
        for (int e = 0; e < 8; e++) gv[e] = gs[e][h * 32 + lane];
#pragma unroll
        for (int i = 0; i < 8; i++)
#pragma unroll
            for (int e = 0; e < 8; e++) acc[i][e] += xv[i] * gv[e];
    }

#pragma unroll
    for (int off = 16; off > 0; off >>= 1)
#pragma unroll
        for (int i = 0; i < 8; i++)
#pragma unroll
            for (int e = 0; e < 8; e++)
                acc[i][e] += __shfl_xor_sync(0xffffffffu, acc[i][e], off);

#pragma unroll
    for (int i = 0; i < 8; i++) {
        if (lane == i) {
            int tok = tok0 + i;
            size_t base = ((size_t)blockIdx.y * T_TOK + tok) * N_EXP;
#pragma unroll
            for (int e = 0; e < 8; e++) lp[base + e] = acc[i][e];
        }
    }
}

// ---------------------------------------------------------------------------
// Gate finalize + scatter into per-(slot,expert) lists.
// ---------------------------------------------------------------------------
__global__ __launch_bounds__(256) void gate_fin(const float* __restrict__ lp,
                                                int* __restrict__ cnt,
                                                int* __restrict__ list,
                                                float* __restrict__ wl)
{
    const int tok = blockIdx.x * 256 + threadIdx.x;
    float l[8];
#pragma unroll
    for (int e = 0; e < 8; e++) l[e] = 0.f;
#pragma unroll
    for (int s = 0; s < KSPLIT; s++) {
        size_t base = ((size_t)s * T_TOK + tok) * N_EXP;
#pragma unroll
        for (int e = 0; e < 8; e++) l[e] += lp[base + e];
    }
    float m1 = -1e30f; int e1 = 0;
#pragma unroll
    for (int e = 0; e < 8; e++)
        if (l[e] > m1) { m1 = l[e]; e1 = e; }
    float m2 = -1e30f; int e2 = 0;
#pragma unroll
    for (int e = 0; e < 8; e++)
        if (e != e1 && l[e] > m2) { m2 = l[e]; e2 = e; }
    float w1 = 1.0f / (1.0f + __expf(m2 - m1));

    int p1 = atomicAdd(&cnt[e1], 1);               // slot 0
    list[e1 * T_TOK + p1] = tok;
    wl[e1 * T_TOK + p1] = w1;
    int p2 = atomicAdd(&cnt[8 + e2], 1);           // slot 1
    list[(8 + e2) * T_TOK + p2] = tok;
    wl[(8 + e2) * T_TOK + p2] = 1.0f - w1;
}

// ---------------------------------------------------------------------------
// GEMM1 sparse — frozen (74.5us plateau; issue-structural).
// ---------------------------------------------------------------------------
#define G1_AT (128 * 36)
#define G1_BT (64 * 36)
#define G1_ST (G1_AT + G1_BT)
#define G1_DYN (2 * G1_ST * 4)

__global__ __launch_bounds__(128, 4) void gemm1_sparse(const float* __restrict__ x,
                                                       const float* __restrict__ Ar,
                                                       const int* __restrict__ cnt,
                                                       const int* __restrict__ list,
                                                       float* __restrict__ Hp)
{
    const int bx  = blockIdx.x;
    const int ks  = bx >> 10;
    const int rem = bx & 1023;
    const int le  = rem >> 6;
    const int mt  = rem & (MAXTIL - 1);
    const int n   = cnt[le];
    if (mt * 128 >= n) return;
    const int e = le & 7;

    __shared__ int toks[128];
    extern __shared__ float sm[];

    const int tid  = threadIdx.x;
    const int lane = tid & 31;
    const int warp = tid >> 5;
    const int wm   = warp >> 1;
    const int wn   = warp & 1;

    toks[tid] = list[le * T_TOK + mt * 128 + tid];
    __syncthreads();

    const uint32_t smbase = (uint32_t)__cvta_generic_to_shared(sm);
    const int lr4 = tid >> 3;
    const int lc4 = (tid & 7) * 4;
    const int kb  = ks * KCHUNK;

    const float* ap[8];
#pragma unroll
    for (int j = 0; j < 8; j++)
        ap[j] = &x[(size_t)toks[lr4 + j * 16] * DMODEL + kb + lc4];
    const float* bp[4];
#pragma unroll
    for (int j = 0; j < 4; j++)
        bp[j] = &Ar[((size_t)e * 64 + lr4 + j * 16) * DMODEL + kb + lc4];

    auto issue = [&](int kt) {
        const int s = kt & 1;
        const int k0 = kt * 32;
        const uint32_t sa = smbase + (uint32_t)(s * G1_ST) * 4u;
        const uint32_t sb = sa + G1_AT * 4u;
#pragma unroll
        for (int j = 0; j < 8; j++)
            cp_async16(sa + ((lr4 + j * 16) * 36 + lc4) * 4u, ap[j] + k0);
#pragma unroll
        for (int j = 0; j < 4; j++)
            cp_async16(sb + ((lr4 + j * 16) * 36 + lc4) * 4u, bp[j] + k0);
    };

    float c[4][4][4] = {};
    issue(0); cp_commit();

    const int r0 = lane >> 2;
    const int cq = lane & 3;
    constexpr int KT = KCHUNK / 32;

    for (int kt = 0; kt < KT; kt++) {
        if (kt + 1 < KT) { issue(kt + 1); cp_commit(); cp_wait<1>(); }
        else             { cp_wait<0>(); }
        __syncthreads();

        const float* As = sm + (kt & 1) * G1_ST;
        const float* Bs = As + G1_AT;

#pragma unroll
        for (int kk = 0; kk < 4; kk++) {
            const int k8 = kk * 8;
            unsigned a[4][4], b[4][2];
#pragma unroll
            for (int mi = 0; mi < 4; mi++) {
                int rb = wm * 64 + mi * 16 + r0;
                a[mi][0] = __float_as_uint(As[rb * 36 + k8 + cq]);
                a[mi][1] = __float_as_uint(As[(rb + 8) * 36 + k8 + cq]);
                a[mi][2] = __float_as_uint(As[rb * 36 + k8 + cq + 4]);
                a[mi][3] = __float_as_uint(As[(rb + 8) * 36 + k8 + cq + 4]);
            }
#pragma unroll
            for (int ni = 0; ni < 4; ni++) {
                int nb = wn * 32 + ni * 8 + r0;
                b[ni][0] = __float_as_uint(Bs[nb * 36 + k8 + cq]);
                b[ni][1] = __float_as_uint(Bs[nb * 36 + k8 + cq + 4]);
            }
#pragma unroll
            for (int mi = 0; mi < 4; mi++)
#pragma unroll
                for (int ni = 0; ni < 4; ni++)
                    mma_tf32(c[mi][ni], a[mi], b[ni]);
        }
        __syncthreads();
    }

    const size_t base = (size_t)ks * HP_STRIDE + ((size_t)le * T_TOK + mt * 128) * RANK;
#pragma unroll
    for (int mi = 0; mi < 4; mi++) {
#pragma unroll
        for (int ni = 0; ni < 4; ni++) {
            int row = wm * 64 + mi * 16 + r0;
            int col = wn * 32 + ni * 8 + cq * 2;
            *(float2*)&Hp[base + (size_t)row * RANK + col] =
                make_float2(c[mi][ni][0], c[mi][ni][1]);
            *(float2*)&Hp[base + (size_t)(row + 8) * RANK + col] =
                make_float2(c[mi][ni][2], c[mi][ni][3]);
        }
    }
}

// ---------------------------------------------------------------------------
// reduce_H: H[le][i] = round( w_i * sum_ks Hp[ks][le][i] )
// ---------------------------------------------------------------------------
__global__ __launch_bounds__(256) void reduce_H(const float* __restrict__ Hp,
                                                const int* __restrict__ cnt,
                                                const float* __restrict__ wl,
                                                float* __restrict__ H)
{
    const int le = blockIdx.x >> 6;
    const int mt = blockIdx.x & (MAXTIL - 1);
    const int n  = cnt[le];
    if (mt * 128 >= n) return;

    const int tid  = threadIdx.x;
    const int row  = tid >> 1;
    const int half = (tid & 1) * 32;
    const int i    = mt * 128 + row;
    if (i >= n) return;

    const float w = wl[le * T_TOK + i];
    const size_t rb = ((size_t)le * T_TOK + i) * RANK + half;

#pragma unroll
    for (int q = 0; q < 8; q++) {
        float4 s = *(const float4*)&Hp[rb + q * 4];
#pragma unroll
        for (int ks = 1; ks < KS1; ks++) {
            float4 p = *(const float4*)&Hp[(size_t)ks * HP_STRIDE + rb + q * 4];
            s.x += p.x; s.y += p.y; s.z += p.z; s.w += p.w;
        }
        s.x = __uint_as_float(f2tf(s.x * w));
        s.y = __uint_as_float(f2tf(s.y * w));
        s.z = __uint_as_float(f2tf(s.z * w));
        s.w = __uint_as_float(f2tf(s.w * w));
        *(float4*)&H[rb + q * 4] = s;
    }
}

// ---------------------------------------------------------------------------
// GEMM2 sparse: 4 N-tiles per CTA, H loaded ONCE, B ring double-buffered.
// SLOT 0: out[tok] = v (STG).  SLOT 1: out[tok] += v via LDG+FADD+STG with
// the out-LDGs hoisted BEFORE the staging barriers.
// ---------------------------------------------------------------------------
#define NT2   4                          // N-tiles per CTA
#define G2_HT (128 * 68)                 // floats per tile buffer
#define G2_DYN (3 * G2_HT * 4)           // H + Bb0 + Bb1 = 104448 B
#define SO_S  132                        // staging row stride (floats)

template <int SLOT>
__global__ __launch_bounds__(256, 2) void gemm2_sparse(const float* __restrict__ H,
                                                       const float* __restrict__ Br,
                                                       const int* __restrict__ cnt,
                                                       const int* __restrict__ list,
                                                       float* __restrict__ out)
{
    const int e  = blockIdx.y >> 6;
    const int le = SLOT * 8 + e;
    const int mt = blockIdx.y & (MAXTIL - 1);
    const int n  = cnt[le];
    if (mt * 128 >= n) return;
    const int bn0 = blockIdx.x * (NT2 * 128);

    __shared__ int toks[128];
    extern __shared__ float sm[];
    float* Hs = sm;                       // H tile (persistent)

    const int tid  = threadIdx.x;
    const int lane = tid & 31;
    const int warp = tid >> 5;
    const int wm   = warp >> 2;
    const int wn   = warp & 3;

    if (tid < 128) toks[tid] = list[le * T_TOK + mt * 128 + tid];

    const uint32_t smbase = (uint32_t)__cvta_generic_to_shared(sm);
    const int lr4 = tid >> 4;          // 0..15
    const int lc4 = (tid & 15) * 4;    // 0..60

    auto issueB = [&](int t) {
        const uint32_t boff = (uint32_t)((1 + (t & 1)) * G2_HT) * 4u;
#pragma unroll
        for (int j = 0; j < 8; j++) {
            int row = lr4 + j * 16;
            cp_async16(smbase + boff + (uint32_t)(row * 68 + lc4) * 4u,
                       &Br[((size_t)e * DMODEL + bn0 + t * 128 + row) * RANK + lc4]);
        }
    };

    // G0 = {H, B0}
#pragma unroll
    for (int j = 0; j < 8; j++) {
        int row = lr4 + j * 16;
        cp_async16(smbase + (uint32_t)(row * 68 + lc4) * 4u,
                   &H[((size_t)le * T_TOK + mt * 128 + row) * RANK + lc4]);
    }
    issueB(0);
    cp_commit();
    // G1 = {B1}
    issueB(1);
    cp_commit();

    const int r0 = lane >> 2;
    const int cq = lane & 3;
    const int rr = tid >> 3;            // 0..31 (epilogue row)
    const int kk8 = (tid & 7) * 4;      // 0..28

#pragma unroll 1
    for (int t = 0; t < NT2; t++) {
        if (t < NT2 - 1) cp_wait<1>();  // B(t) (and H for t=0) complete
        else             cp_wait<0>();
        __syncthreads();

        const float* Bs = sm + (1 + (t & 1)) * G2_HT;
        float* so = sm + (1 + (t & 1)) * G2_HT;   // staging = this tile's B buf
        const int bn = bn0 + t * 128;

        float c[4][4][4] = {};
#pragma unroll
        for (int kk = 0; kk < 8; kk++) {
            const int k8 = kk * 8;
            unsigned a[4][4], b[4][2];
#pragma unroll
            for (int mi = 0; mi < 4; mi++) {
                int rb = wm * 64 + mi * 16 + r0;
                a[mi][0] = __float_as_uint(Hs[rb * 68 + k8 + cq]);
                a[mi][1] = __float_as_uint(Hs[(rb + 8) * 68 + k8 + cq]);
                a[mi][2] = __float_as_uint(Hs[rb * 68 + k8 + cq + 4]);
                a[mi][3] = __float_as_uint(Hs[(rb + 8) * 68 + k8 + cq + 4]);
            }
#pragma unroll
            for (int ni = 0; ni < 4; ni++) {
                int nb = wn * 32 + ni * 8 + r0;
                b[ni][0] = __float_as_uint(Bs[nb * 68 + k8 + cq]);
                b[ni][1] = __float_as_uint(Bs[nb * 68 + k8 + cq + 4]);
            }
#pragma unroll
            for (int mi = 0; mi < 4; mi++)
#pragma unroll
                for (int ni = 0; ni < 4; ni++)
                    mma_tf32(c[mi][ni], a[mi], b[ni]);
        }

        // ---- staged coalesced epilogue: 4 groups of 32 rows ----
#pragma unroll
        for (int g = 0; g < 4; g++) {
            const int gi = mt * 128 + g * 32 + rr;
            const bool valid = gi < n;
            float* op = nullptr;
            float4 o[4];
            if (valid) {
                const int tk = toks[g * 32 + rr];
                op = &out[(size_t)tk * DMODEL + bn + kk8];
                if (SLOT == 1) {
                    // hoisted loads: overlap with staging barriers below
#pragma unroll
                    for (int q = 0; q < 4; q++) o[q] = *(const float4*)&op[q * 32];
                }
            }
            __syncthreads();
            if (wm == (g >> 1)) {
                const int m0 = (g & 1) * 2;
#pragma unroll
                for (int mh = 0; mh < 2; mh++) {
                    const int mi = m0 + mh;
                    const int rl = mh * 16 + r0;
#pragma unroll
                    for (int ni = 0; ni < 4; ni++) {
                        const int col = wn * 32 + ni * 8 + cq * 2;
                        *(float2*)&so[rl * SO_S + col] =
                            make_float2(c[mi][ni][0], c[mi][ni][1]);
                        *(float2*)&so[(rl + 8) * SO_S + col] =
                            make_float2(c[mi][ni][2], c[mi][ni][3]);
                    }
                }
            }
            __syncthreads();
            if (valid) {
#pragma unroll
                for (int q = 0; q < 4; q++) {
                    float4 v = *(float4*)&so[rr * SO_S + kk8 + q * 32];
                    if (SLOT == 1) {
                        v.x += o[q].x; v.y += o[q].y; v.z += o[q].z; v.w += o[q].w;
                    }
                    *(float4*)&op[q * 32] = v;
                }
            }
        }
        __syncthreads();   // epilogue drained before buffer (t&1) is refilled

        if (t + 2 < NT2) { issueB(t + 2); cp_commit(); }
    }
}

// ---------------------------------------------------------------------------
// launch
// ---------------------------------------------------------------------------
extern "C" void kernel_launch(void* const* d_in, const int* in_sizes, int n_in,
                              void* d_out, int out_size)
{
    const float* x  = (const float*)d_in[0];   // [4,2048,4096]
    const float* gw = (const float*)d_in[1];   // [8,4096]
    const float* lA = (const float*)d_in[2];   // [8,64,4096]
    const float* lB = (const float*)d_in[3];   // [8,4096,64]
    float* out = (float*)d_out;

    float *Hp, *Hc, *lpp, *Ar, *Br, *wlp;
    int *cntp, *listp;
    cudaGetSymbolAddress((void**)&Hp,   g_Hp);
    cudaGetSymbolAddress((void**)&Hc,   g_H);
    cudaGetSymbolAddress((void**)&lpp,  g_lp);
    cudaGetSymbolAddress((void**)&Ar,   g_Ar);
    cudaGetSymbolAddress((void**)&Br,   g_Br);
    cudaGetSymbolAddress((void**)&cntp, g_cnt);
    cudaGetSymbolAddress((void**)&listp,g_list);
    cudaGetSymbolAddress((void**)&wlp,  g_wl);

    cudaFuncSetAttribute((const void*)gemm1_sparse,
                         cudaFuncAttributeMaxDynamicSharedMemorySize, G1_DYN);
    cudaFuncSetAttribute((const void*)gemm2_sparse<0>,
                         cudaFuncAttributeMaxDynamicSharedMemorySize, G2_DYN);
    cudaFuncSetAttribute((const void*)gemm2_sparse<1>,
                         cudaFuncAttributeMaxDynamicSharedMemorySize, G2_DYN);

    // 1) gate partials (K-split x8) + fused weight rounding + counter reset
    gate_part<<<dim3(T_TOK / 64, KSPLIT + 1), 256>>>(
        x, gw, lpp, (const float4*)lA, (const float4*)lB,
        (float4*)Ar, (float4*)Br, cntp);
    // 2) finalize gate + scatter tokens into (slot, expert) lists
    gate_fin<<<T_TOK / 256, 256>>>(lpp, cntp, listp, wlp);
    // 3) sparse GEMM1 (frozen)
    gemm1_sparse<<<KS1 * NLIST * MAXTIL, 128, G1_DYN>>>(x, Ar, cntp, listp, Hp);
    // 4) reduce partials + routing weight + tf32-round -> compact H
    reduce_H<<<NLIST * MAXTIL, 256>>>(Hp, cntp, wlp, Hc);
    // 5) sparse GEMM2 pass A (slot 0): out = v
    gemm2_sparse<0><<<dim3(DMODEL / (NT2 * 128), N_EXP * MAXTIL), 256, G2_DYN>>>(Hc, Br, cntp, listp, out);
    // 6) sparse GEMM2 pass B (slot 1): out += v (hoisted out-loads)
    gemm2_sparse<1><<<dim3(DMODEL / (NT2 * 128), N_EXP * MAXTIL), 256, G2_DYN>>>(Hc, Br, cntp, listp, out);
}